// round 4
// baseline (speedup 1.0000x reference)
#include <cuda_runtime.h>
#include <cuda_fp16.h>
#include <cstdint>
#include <math.h>

// Problem constants (fixed shapes for this problem)
#define PDIM   128              // n_proxy_sets
#define EDIM   32               // elements per proxy set
#define DDIM   64               // feature dim
#define PE     (PDIM*EDIM)      // 4096 flattened proxies
#define NCHUNK 64               // proxies per inner chunk (= 2 full p-groups)
#define NCHUNKS (PE/NCHUNK)     // 64
#define TILE_M 128              // x rows per tile (= SEG_LEN here)
#define XPITCH 72               // padded fp16 row pitch (conflict-free ldmatrix)
#define WPITCH 72
#define THREADS 256
#define MAXB   1024

// Scratch (no cudaMalloc allowed)
__device__ __half g_wh[PE * DDIM];   // 512 KB fp16 proxies, stays hot in L2
__device__ int g_segoff[MAXB];

// ---------------- helper kernels ----------------

// fp32 -> fp16 proxy conversion, 8 elems/thread, vectorized
__global__ void convw_kernel(const float* __restrict__ w, int n8) {
    int i = blockIdx.x * blockDim.x + threadIdx.x;
    if (i < n8) {
        float4 a = __ldg((const float4*)w + 2 * i);
        float4 b = __ldg((const float4*)w + 2 * i + 1);
        __half2 h0 = __floats2half2_rn(a.x, a.y);
        __half2 h1 = __floats2half2_rn(a.z, a.w);
        __half2 h2 = __floats2half2_rn(b.x, b.y);
        __half2 h3 = __floats2half2_rn(b.z, b.w);
        uint4 pk;
        pk.x = *(uint32_t*)&h0; pk.y = *(uint32_t*)&h1;
        pk.z = *(uint32_t*)&h2; pk.w = *(uint32_t*)&h3;
        *((uint4*)g_wh + i) = pk;
    }
}

// exclusive prefix sum of segment lengths (B <= 1024, single block)
__global__ void scan_kernel(const int* __restrict__ index, int B) {
    __shared__ int s[MAXB];
    int t = threadIdx.x;
    int v = (t < B) ? index[t] : 0;
    s[t] = v;
    __syncthreads();
    for (int o = 1; o < MAXB; o <<= 1) {
        int add = (t >= o) ? s[t - o] : 0;
        __syncthreads();
        s[t] += add;
        __syncthreads();
    }
    if (t < B) g_segoff[t] = s[t] - v;
}

// ---------------- MMA / packed-math primitives ----------------

__device__ __forceinline__ void ldsm_x4(uint32_t& r0, uint32_t& r1,
                                        uint32_t& r2, uint32_t& r3,
                                        const void* p) {
    uint32_t a = (uint32_t)__cvta_generic_to_shared(p);
    asm volatile("ldmatrix.sync.aligned.m8n8.x4.shared.b16 {%0,%1,%2,%3}, [%4];"
                 : "=r"(r0), "=r"(r1), "=r"(r2), "=r"(r3) : "r"(a));
}

// f16 inputs, f16 accumulators (2 packed regs)
__device__ __forceinline__ void mma_f16(uint32_t* c, const uint32_t* a,
                                        uint32_t b0, uint32_t b1) {
    asm volatile(
        "mma.sync.aligned.m16n8k16.row.col.f16.f16.f16.f16 "
        "{%0,%1}, {%2,%3,%4,%5}, {%6,%7}, {%0,%1};"
        : "+r"(c[0]), "+r"(c[1])
        : "r"(a[0]), "r"(a[1]), "r"(a[2]), "r"(a[3]), "r"(b0), "r"(b1));
}

__device__ __forceinline__ uint32_t hmax2(uint32_t a, uint32_t b) {
    uint32_t d;
    asm("max.f16x2 %0, %1, %2;" : "=r"(d) : "r"(a), "r"(b));
    return d;
}

__device__ __forceinline__ float h_lo_f32(uint32_t v) {
    return __half2float(__ushort_as_half((unsigned short)(v & 0xffffu)));
}

// ---------------- main kernel ----------------
// One CTA per segment. M=128 x-rows (fp16 in smem, A-frags pinned in regs),
// sweep 4096 proxies in chunks of 64 (double-buffered smem, 1 barrier/chunk),
// f16-accumulator MMA, packed-f16x2 max epilogue, smem atomic accumulate into
// pooled[P], then in-block L2 normalize.

__global__ __launch_bounds__(THREADS, 2)
void main_kernel(const float* __restrict__ x, const int* __restrict__ index,
                 float* __restrict__ out) {
    __shared__ __half xs[TILE_M * XPITCH];          // 18 KB
    __shared__ __half ws[2][NCHUNK * WPITCH];       // 2 x 9 KB double buffer
    __shared__ float pooled[PDIM];
    __shared__ float red[8];

    const int b    = blockIdx.x;
    const int tid  = threadIdx.x;
    const int lane = tid & 31;
    const int warp = tid >> 5;

    for (int i = tid; i < PDIM; i += THREADS) pooled[i] = 0.f;

    const int off = g_segoff[b];
    const int len = index[b];

    for (int tile = 0; tile * TILE_M < len; ++tile) {
        __syncthreads();   // pooled-init / previous-tile drain
        // ---- load + convert x tile to fp16 (zero-pad ragged tail) ----
        {
            int row  = tid >> 1;
            int half = tid & 1;
            int rrem = len - tile * TILE_M;
            bool valid = row < rrem;
            const float* xr = x + ((size_t)(off + tile * TILE_M + row)) * DDIM + half * 32;
            __half2* dst = (__half2*)&xs[row * XPITCH + half * 32];
            #pragma unroll
            for (int j = 0; j < 8; ++j) {
                float4 v = valid ? __ldg((const float4*)xr + j)
                                 : make_float4(0.f, 0.f, 0.f, 0.f);
                dst[2 * j]     = __floats2half2_rn(v.x, v.y);
                dst[2 * j + 1] = __floats2half2_rn(v.z, v.w);
            }
        }
        __syncthreads();

        // ---- A fragments: 16 rows per warp, K=64 (4 k-steps), pinned in regs ----
        uint32_t afr[4][4];
        {
            const __half* base =
                &xs[(warp * 16 + (lane & 15)) * XPITCH + (lane >> 4) * 8];
            #pragma unroll
            for (int k = 0; k < 4; ++k)
                ldsm_x4(afr[k][0], afr[k][1], afr[k][2], afr[k][3], base + k * 16);
        }

        // ---- register-prefetch chunk 0 proxy tile (64x64 fp16 = 8KB) ----
        uint4 w0, w1;
        {
            int u0 = tid, u1 = tid + 256;
            w0 = *((const uint4*)(g_wh + (u0 >> 3) * DDIM) + (u0 & 7));
            w1 = *((const uint4*)(g_wh + (u1 >> 3) * DDIM) + (u1 & 7));
        }

        for (int c = 0; c < NCHUNKS; ++c) {
            __half* wbuf = ws[c & 1];
            // stage chunk c (hazard vs reads at c-2 is covered by sync at c-1)
            {
                int u0 = tid, u1 = tid + 256;
                *((uint4*)&wbuf[(u0 >> 3) * WPITCH + (u0 & 7) * 8]) = w0;
                *((uint4*)&wbuf[(u1 >> 3) * WPITCH + (u1 & 7) * 8]) = w1;
            }
            __syncthreads();
            if (c + 1 < NCHUNKS) {  // prefetch next chunk while computing this one
                int u0 = tid, u1 = tid + 256;
                const __half* wb = g_wh + (size_t)(c + 1) * NCHUNK * DDIM;
                w0 = *((const uint4*)(wb + (u0 >> 3) * DDIM) + (u0 & 7));
                w1 = *((const uint4*)(wb + (u1 >> 3) * DDIM) + (u1 & 7));
            }

            // ---- 16x64x64 per warp: 32 HMMAs, f16 accumulators ----
            uint32_t acc[8][2];
            #pragma unroll
            for (int nt = 0; nt < 8; ++nt) { acc[nt][0] = 0u; acc[nt][1] = 0u; }
            #pragma unroll
            for (int k = 0; k < 4; ++k) {
                uint32_t bfr[16];
                #pragma unroll
                for (int ng = 0; ng < 4; ++ng) {
                    const __half* bp =
                        &wbuf[(ng * 16 + (lane & 15)) * WPITCH + k * 16 + (lane >> 4) * 8];
                    ldsm_x4(bfr[ng * 4], bfr[ng * 4 + 1], bfr[ng * 4 + 2], bfr[ng * 4 + 3], bp);
                }
                #pragma unroll
                for (int nt = 0; nt < 8; ++nt) {
                    int ng = nt >> 1, sub = nt & 1;
                    mma_f16(acc[nt], afr[k], bfr[ng * 4 + sub], bfr[ng * 4 + 2 + sub]);
                }
            }

            // ---- fused epilogue, packed f16x2 ----
            // acc[nt][0] = row g, cols {2c,2c+1}; acc[nt][1] = row g+8.
            // Max over 32 cols of each p-group, then sum rows, atomically into pooled.
            #pragma unroll
            for (int pg = 0; pg < 2; ++pg) {
                uint32_t* a0 = acc[pg * 4 + 0];
                uint32_t* a1 = acc[pg * 4 + 1];
                uint32_t* a2 = acc[pg * 4 + 2];
                uint32_t* a3 = acc[pg * 4 + 3];
                uint32_t lo = hmax2(hmax2(a0[0], a1[0]), hmax2(a2[0], a3[0]));
                uint32_t hi = hmax2(hmax2(a0[1], a1[1]), hmax2(a2[1], a3[1]));
                // max across the 4 lanes of the quad (covers all 32 cols, packed)
                lo = hmax2(lo, __shfl_xor_sync(0xffffffffu, lo, 1));
                hi = hmax2(hi, __shfl_xor_sync(0xffffffffu, hi, 1));
                lo = hmax2(lo, __shfl_xor_sync(0xffffffffu, lo, 2));
                hi = hmax2(hi, __shfl_xor_sync(0xffffffffu, hi, 2));
                // fold the two packed halves (even/odd column parities)
                lo = hmax2(lo, __byte_perm(lo, lo, 0x1032));
                hi = hmax2(hi, __byte_perm(hi, hi, 0x1032));
                // sum of the two row-maxes (rows g and g+8), f32 from here
                float s = h_lo_f32(lo) + h_lo_f32(hi);
                s += __shfl_xor_sync(0xffffffffu, s, 4);
                s += __shfl_xor_sync(0xffffffffu, s, 8);
                s += __shfl_xor_sync(0xffffffffu, s, 16);  // sum of all 16 rows
                if (lane == 0) atomicAdd(&pooled[c * 2 + pg], s);
            }
        }
    }

    // ---- L2 normalize pooled[0..127] and emit ----
    __syncthreads();
    float v = 0.f, s2 = 0.f;
    if (tid < PDIM) { v = pooled[tid]; s2 = v * v; }
    #pragma unroll
    for (int o = 16; o > 0; o >>= 1) s2 += __shfl_xor_sync(0xffffffffu, s2, o);
    if (lane == 0) red[warp] = s2;
    __syncthreads();
    if (tid < PDIM) {
        float n2  = red[0] + red[1] + red[2] + red[3];
        float nrm = sqrtf(n2);
        out[(size_t)b * PDIM + tid] = v / fmaxf(nrm, 1e-12f);
    }
}

// ---------------- launch ----------------

extern "C" void kernel_launch(void* const* d_in, const int* in_sizes, int n_in,
                              void* d_out, int out_size) {
    const float* x     = (const float*)d_in[0];
    const float* w     = (const float*)d_in[1];
    const int*   index = (const int*)d_in[2];
    float* out = (float*)d_out;

    int nw = in_sizes[1];            // P*E*D = 262144
    int B  = in_sizes[2];            // 1024

    int n8 = nw / 8;
    convw_kernel<<<(n8 + 255) / 256, 256>>>(w, n8);
    scan_kernel<<<1, MAXB>>>(index, B);
    main_kernel<<<B, THREADS>>>(x, index, out);
}

// round 6
// speedup vs baseline: 2.0913x; 2.0913x over previous
#include <cuda_runtime.h>
#include <cuda_bf16.h>
#include <cstdint>
#include <math.h>

// ---------------- problem constants ----------------
#define PDIM   128              // n_proxy_sets
#define EDIM   32               // elements per proxy set
#define DDIM   64               // feature dim
#define PE     (PDIM*EDIM)      // 4096 flattened proxies
#define NCHUNK 64               // proxies per chunk (= 2 proxy sets)
#define NCHUNKS (PE/NCHUNK)     // 64
#define TILE_M 128              // x rows per tile (= SEG_LEN here)
#define XPITCH 72               // padded bf16 row pitch (conflict-free ldsm)
#define WPITCH 72
#define THREADS 256
#define MAXB   1024

__device__ __nv_bfloat16 g_wbf[PE * DDIM];   // 512 KB bf16 proxies (L2-hot)
__device__ int g_segoff[MAXB];

// ---------------- prep kernel: w conversion + segment-offset scan ----------------
// blocks 0..127: fp32->bf16 proxy conversion (8 floats per thread, vectorized)
// block 128: exclusive prefix sum of segment lengths
__global__ void prep_kernel(const float* __restrict__ w, int n8,
                            const int* __restrict__ index, int B) {
    if (blockIdx.x < 128) {
        int i = blockIdx.x * blockDim.x + threadIdx.x;
        if (i < n8) {
            float4 a = __ldg((const float4*)w + 2 * i);
            float4 b = __ldg((const float4*)w + 2 * i + 1);
            __nv_bfloat162 h0 = __floats2bfloat162_rn(a.x, a.y);
            __nv_bfloat162 h1 = __floats2bfloat162_rn(a.z, a.w);
            __nv_bfloat162 h2 = __floats2bfloat162_rn(b.x, b.y);
            __nv_bfloat162 h3 = __floats2bfloat162_rn(b.z, b.w);
            uint4 pk;
            pk.x = *(uint32_t*)&h0; pk.y = *(uint32_t*)&h1;
            pk.z = *(uint32_t*)&h2; pk.w = *(uint32_t*)&h3;
            *((uint4*)g_wbf + i) = pk;
        }
    } else {
        __shared__ int s[MAXB];
        // 256 threads scan up to 1024 entries: serial-per-thread chunks of 4 + scan
        int t = threadIdx.x;
        int v[4]; int base = t * 4;
        int acc = 0;
        #pragma unroll
        for (int j = 0; j < 4; ++j) {
            v[j] = acc;
            int e = base + j;
            acc += (e < B) ? index[e] : 0;
        }
        s[t] = acc;                 // chunk total (reuse s[0..255])
        __syncthreads();
        // scan of 256 chunk totals
        for (int o = 1; o < 256; o <<= 1) {
            int add = (t >= o) ? s[t - o] : 0;
            __syncthreads();
            s[t] += add;
            __syncthreads();
        }
        int pre = (t > 0) ? s[t - 1] : 0;
        #pragma unroll
        for (int j = 0; j < 4; ++j) {
            int e = base + j;
            if (e < B) g_segoff[e] = pre + v[j];
        }
    }
}

// ---------------- MMA primitives ----------------
__device__ __forceinline__ void ldsm_x4(uint32_t& r0, uint32_t& r1,
                                        uint32_t& r2, uint32_t& r3,
                                        const void* p) {
    uint32_t a = (uint32_t)__cvta_generic_to_shared(p);
    asm volatile("ldmatrix.sync.aligned.m8n8.x4.shared.b16 {%0,%1,%2,%3}, [%4];"
                 : "=r"(r0), "=r"(r1), "=r"(r2), "=r"(r3) : "r"(a));
}

__device__ __forceinline__ void mma_bf16(float* c, const uint32_t* a,
                                         uint32_t b0, uint32_t b1) {
    asm volatile(
        "mma.sync.aligned.m16n8k16.row.col.f32.bf16.bf16.f32 "
        "{%0,%1,%2,%3}, {%4,%5,%6,%7}, {%8,%9}, {%0,%1,%2,%3};"
        : "+f"(c[0]), "+f"(c[1]), "+f"(c[2]), "+f"(c[3])
        : "r"(a[0]), "r"(a[1]), "r"(a[2]), "r"(a[3]), "r"(b0), "r"(b1));
}

#define CP16(dst, src)  asm volatile("cp.async.cg.shared.global [%0], [%1], 16;" :: "r"(dst), "l"(src) : "memory")
#define CP_COMMIT()     asm volatile("cp.async.commit_group;" ::: "memory")
#define CP_WAIT0()      asm volatile("cp.async.wait_group 0;" ::: "memory")

// ---------------- main kernel ----------------
// One CTA per segment, 8 warps. Warp tile = 32 rows x 32 cols.
// warp w: rows (w&3)*32..+31, proxy-group pg = w>>2 (global p = 2c + pg).
// A (x tile, bf16, smem) frags pinned in regs across all 64 chunks.
// B (proxies) double-buffered via cp.async, 1 barrier per chunk.
// Fused epilogue: per-row max over 32 cols -> quad shuffle max -> row-sum ->
// smem atomicAdd into pooled[p]. Then in-block L2 normalize.
__global__ __launch_bounds__(THREADS, 2)
void main_kernel(const float* __restrict__ x, const int* __restrict__ index,
                 float* __restrict__ out) {
    __shared__ __nv_bfloat16 xs[TILE_M * XPITCH];     // 18 KB
    __shared__ __nv_bfloat16 ws[2][NCHUNK * WPITCH];  // 2 x 9 KB
    __shared__ float pooled[PDIM];
    __shared__ float red[8];

    const int b    = blockIdx.x;
    const int tid  = threadIdx.x;
    const int lane = tid & 31;
    const int warp = tid >> 5;
    const int rgrp = warp & 3;     // row-group (32 rows)
    const int pg   = warp >> 2;    // proxy-group within chunk (0/1)

    if (tid < PDIM) pooled[tid] = 0.f;

    const int off = g_segoff[b];
    const int len = index[b];

    uint32_t sm_ws0 = (uint32_t)__cvta_generic_to_shared(&ws[0][0]);
    uint32_t sm_ws1 = (uint32_t)__cvta_generic_to_shared(&ws[1][0]);

    for (int tile = 0; tile * TILE_M < len; ++tile) {
        __syncthreads();   // pooled-init / previous-tile drain
        // ---- stage x tile to bf16 smem (zero-pad ragged tail) ----
        {
            int row  = tid >> 1;
            int half = tid & 1;
            int rrem = len - tile * TILE_M;
            bool valid = row < rrem;
            const float* xr = x + ((size_t)(off + tile * TILE_M + row)) * DDIM + half * 32;
            __nv_bfloat162* dst = (__nv_bfloat162*)&xs[row * XPITCH + half * 32];
            #pragma unroll
            for (int j = 0; j < 8; ++j) {
                float4 v = valid ? __ldg((const float4*)xr + j)
                                 : make_float4(0.f, 0.f, 0.f, 0.f);
                dst[2 * j]     = __floats2bfloat162_rn(v.x, v.y);
                dst[2 * j + 1] = __floats2bfloat162_rn(v.z, v.w);
            }
        }
        // ---- issue cp.async for chunk 0 while A-staging settles ----
        {
            const char* src = (const char*)g_wbf;   // chunk 0
            #pragma unroll
            for (int j = 0; j < 2; ++j) {
                uint32_t u = tid + THREADS * j;      // 16B unit, 512 total
                uint32_t row = u >> 3, cu = u & 7;
                CP16(sm_ws0 + row * (WPITCH * 2) + cu * 16, src + (size_t)u * 16);
            }
            CP_COMMIT();
        }
        __syncthreads();   // xs visible

        // ---- A fragments: 32 rows per warp, K=64: 2 mfrags x 4 ksteps ----
        uint32_t afr[2][4][4];
        #pragma unroll
        for (int m = 0; m < 2; ++m) {
            const __nv_bfloat16* base =
                &xs[(rgrp * 32 + m * 16 + (lane & 15)) * XPITCH + (lane >> 4) * 8];
            #pragma unroll
            for (int k = 0; k < 4; ++k)
                ldsm_x4(afr[m][k][0], afr[m][k][1], afr[m][k][2], afr[m][k][3],
                        base + k * 16);
        }

        for (int c = 0; c < NCHUNKS; ++c) {
            CP_WAIT0();        // B(c) arrived (this thread's copies)
            __syncthreads();   // B(c) visible to all; all warps done with B(c-1)

            // prefetch B(c+1) into the other buffer (it held B(c-1), now free)
            if (c + 1 < NCHUNKS) {
                const char* src = (const char*)g_wbf + (size_t)(c + 1) * NCHUNK * DDIM * 2;
                uint32_t bb = ((c + 1) & 1) ? sm_ws1 : sm_ws0;
                #pragma unroll
                for (int j = 0; j < 2; ++j) {
                    uint32_t u = tid + THREADS * j;
                    uint32_t row = u >> 3, cu = u & 7;
                    CP16(bb + row * (WPITCH * 2) + cu * 16, src + (size_t)u * 16);
                }
                CP_COMMIT();
            }

            const __nv_bfloat16* wbuf = ws[c & 1];

            // ---- 32x32x64 per warp: 32 HMMAs ----
            float acc[2][4][4];
            #pragma unroll
            for (int m = 0; m < 2; ++m)
                #pragma unroll
                for (int n = 0; n < 4; ++n)
                    acc[m][n][0] = acc[m][n][1] = acc[m][n][2] = acc[m][n][3] = 0.f;

            #pragma unroll
            for (int k = 0; k < 4; ++k) {
                uint32_t bfr[8];
                #pragma unroll
                for (int h = 0; h < 2; ++h) {
                    const __nv_bfloat16* bp =
                        &wbuf[(pg * 32 + h * 16 + (lane & 15)) * WPITCH
                              + k * 16 + (lane >> 4) * 8];
                    ldsm_x4(bfr[h * 4], bfr[h * 4 + 1], bfr[h * 4 + 2], bfr[h * 4 + 3], bp);
                }
                #pragma unroll
                for (int m = 0; m < 2; ++m)
                    #pragma unroll
                    for (int n = 0; n < 4; ++n) {
                        int h = n >> 1, sub = n & 1;
                        mma_bf16(acc[m][n], afr[m][k],
                                 bfr[h * 4 + sub], bfr[h * 4 + 2 + sub]);
                    }
            }

            // ---- fused epilogue: max over 32 cols per row, sum 32 rows ----
            // acc[m][n][0..1] = row (m*16 + lane/4), cols n*8+{2c,2c+1}
            // acc[m][n][2..3] = row (+8)
            float rm[4];
            #pragma unroll
            for (int m = 0; m < 2; ++m) {
                float lo = fmaxf(fmaxf(fmaxf(acc[m][0][0], acc[m][0][1]),
                                       fmaxf(acc[m][1][0], acc[m][1][1])),
                                 fmaxf(fmaxf(acc[m][2][0], acc[m][2][1]),
                                       fmaxf(acc[m][3][0], acc[m][3][1])));
                float hi = fmaxf(fmaxf(fmaxf(acc[m][0][2], acc[m][0][3]),
                                       fmaxf(acc[m][1][2], acc[m][1][3])),
                                 fmaxf(fmaxf(acc[m][2][2], acc[m][2][3]),
                                       fmaxf(acc[m][3][2], acc[m][3][3])));
                rm[m * 2]     = lo;
                rm[m * 2 + 1] = hi;
            }
            // quad-lane max (covers all 32 cols of this p-group)
            #pragma unroll
            for (int r = 0; r < 4; ++r) {
                rm[r] = fmaxf(rm[r], __shfl_xor_sync(0xffffffffu, rm[r], 1));
                rm[r] = fmaxf(rm[r], __shfl_xor_sync(0xffffffffu, rm[r], 2));
            }
            float s = (rm[0] + rm[1]) + (rm[2] + rm[3]);   // 4 rows per thread
            s += __shfl_xor_sync(0xffffffffu, s, 4);
            s += __shfl_xor_sync(0xffffffffu, s, 8);
            s += __shfl_xor_sync(0xffffffffu, s, 16);      // all 32 rows of warp
            if (lane == 0) atomicAdd(&pooled[c * 2 + pg], s);
        }
    }

    // ---- L2 normalize pooled[0..127] and emit ----
    __syncthreads();
    float v = 0.f, s2 = 0.f;
    if (tid < PDIM) { v = pooled[tid]; s2 = v * v; }
    #pragma unroll
    for (int o = 16; o > 0; o >>= 1) s2 += __shfl_xor_sync(0xffffffffu, s2, o);
    if (lane == 0) red[warp] = s2;
    __syncthreads();
    if (tid < PDIM) {
        float n2  = red[0] + red[1] + red[2] + red[3];
        float nrm = sqrtf(n2);
        out[(size_t)b * PDIM + tid] = v / fmaxf(nrm, 1e-12f);
    }
}

// ---------------- launch ----------------
extern "C" void kernel_launch(void* const* d_in, const int* in_sizes, int n_in,
                              void* d_out, int out_size) {
    const float* x     = (const float*)d_in[0];
    const float* w     = (const float*)d_in[1];
    const int*   index = (const int*)d_in[2];
    float* out = (float*)d_out;

    int nw = in_sizes[1];            // P*E*D = 262144
    int B  = in_sizes[2];            // 1024

    int n8 = nw / 8;                 // 32768 uint4-pairs
    prep_kernel<<<129, 256>>>(w, n8, index, B);
    main_kernel<<<B, THREADS>>>(x, index, out);
}

// round 8
// speedup vs baseline: 2.1910x; 1.0477x over previous
#include <cuda_runtime.h>
#include <cuda_bf16.h>
#include <cstdint>
#include <math.h>

// ---------------- problem constants ----------------
#define PDIM   128              // n_proxy_sets
#define EDIM   32               // elements per proxy set
#define DDIM   64               // feature dim
#define PE     (PDIM*EDIM)      // 4096 flattened proxies
#define NCHUNK 64               // proxies per chunk (= 2 proxy sets)
#define NCH_CTA 32              // chunks per CTA (proxy range split across 2 CTAs)
#define TILE_M 128              // x rows per tile
#define XPITCH 72               // padded bf16 row pitch (conflict-free ldsm)
#define WPITCH 72
#define THREADS 256
#define MAXB   1024

__device__ __nv_bfloat16 g_wbf[PE * DDIM];   // 512 KB bf16 proxies (L2-hot)
__device__ int g_segoff[MAXB];

// ---------------- prep kernel: w conversion + segment-offset scan ----------------
__global__ void prep_kernel(const float* __restrict__ w, int n8,
                            const int* __restrict__ index, int B) {
    if (blockIdx.x < 128) {
        int i = blockIdx.x * blockDim.x + threadIdx.x;
        if (i < n8) {
            float4 a = __ldg((const float4*)w + 2 * i);
            float4 b = __ldg((const float4*)w + 2 * i + 1);
            __nv_bfloat162 h0 = __floats2bfloat162_rn(a.x, a.y);
            __nv_bfloat162 h1 = __floats2bfloat162_rn(a.z, a.w);
            __nv_bfloat162 h2 = __floats2bfloat162_rn(b.x, b.y);
            __nv_bfloat162 h3 = __floats2bfloat162_rn(b.z, b.w);
            uint4 pk;
            pk.x = *(uint32_t*)&h0; pk.y = *(uint32_t*)&h1;
            pk.z = *(uint32_t*)&h2; pk.w = *(uint32_t*)&h3;
            *((uint4*)g_wbf + i) = pk;
        }
    } else {
        __shared__ int s[256];
        int t = threadIdx.x;
        int v[4]; int base = t * 4;
        int acc = 0;
        #pragma unroll
        for (int j = 0; j < 4; ++j) {
            v[j] = acc;
            int e = base + j;
            acc += (e < B) ? index[e] : 0;
        }
        s[t] = acc;
        __syncthreads();
        for (int o = 1; o < 256; o <<= 1) {
            int add = (t >= o) ? s[t - o] : 0;
            __syncthreads();
            s[t] += add;
            __syncthreads();
        }
        int pre = (t > 0) ? s[t - 1] : 0;
        #pragma unroll
        for (int j = 0; j < 4; ++j) {
            int e = base + j;
            if (e < B) g_segoff[e] = pre + v[j];
        }
    }
}

// ---------------- MMA primitives ----------------
__device__ __forceinline__ void ldsm_x4(uint32_t& r0, uint32_t& r1,
                                        uint32_t& r2, uint32_t& r3,
                                        const void* p) {
    uint32_t a = (uint32_t)__cvta_generic_to_shared(p);
    asm volatile("ldmatrix.sync.aligned.m8n8.x4.shared.b16 {%0,%1,%2,%3}, [%4];"
                 : "=r"(r0), "=r"(r1), "=r"(r2), "=r"(r3) : "r"(a));
}

__device__ __forceinline__ void mma_bf16(float* c, const uint32_t* a,
                                         uint32_t b0, uint32_t b1) {
    asm volatile(
        "mma.sync.aligned.m16n8k16.row.col.f32.bf16.bf16.f32 "
        "{%0,%1,%2,%3}, {%4,%5,%6,%7}, {%8,%9}, {%0,%1,%2,%3};"
        : "+f"(c[0]), "+f"(c[1]), "+f"(c[2]), "+f"(c[3])
        : "r"(a[0]), "r"(a[1]), "r"(a[2]), "r"(a[3]), "r"(b0), "r"(b1));
}

#define CP16(dst, src)  asm volatile("cp.async.cg.shared.global [%0], [%1], 16;" :: "r"(dst), "l"(src) : "memory")
#define CP_COMMIT()     asm volatile("cp.async.commit_group;" ::: "memory")
#define CP_WAIT0()      asm volatile("cp.async.wait_group 0;" ::: "memory")

// ---------------- main kernel ----------------
// 2 CTAs per segment (blockIdx = b*2 + half); each CTA sweeps 32 proxy chunks
// (its half of the 4096 proxies). 8 warps: warp = rgrp (rows) x pg (32-proxy
// group). Per h-block (16 cols x 64k) MMA + immediate partial max fold, so
// the max tree overlaps later HMMAs. Per-chunk reduction ends at a quad-max
// + one exclusive-owner smem += (no shuffles-to-lane0, no atomics). CTA-end
// reduction writes unnormalized sums to out; norm_kernel finishes.
__global__ __launch_bounds__(THREADS, 2)
void main_kernel(const float* __restrict__ x, const int* __restrict__ index,
                 float* __restrict__ out) {
    __shared__ __nv_bfloat16 xs[TILE_M * XPITCH];     // 18 KB
    __shared__ __nv_bfloat16 ws[2][NCHUNK * WPITCH];  // 2 x 9 KB
    __shared__ float pooled2[64 * 32];                // 8 KB partials [p_local][slot]

    const int b    = blockIdx.x >> 1;
    const int half = blockIdx.x & 1;
    const int tid  = threadIdx.x;
    const int lane = tid & 31;
    const int warp = tid >> 5;
    const int rgrp = warp & 3;     // row-group (32 rows)
    const int pg   = warp >> 2;    // proxy-group within chunk (0/1)

    for (int i = tid; i < 64 * 32; i += THREADS) pooled2[i] = 0.f;

    const int off = g_segoff[b];
    const int len = index[b];

    uint32_t sm_ws0 = (uint32_t)__cvta_generic_to_shared(&ws[0][0]);
    uint32_t sm_ws1 = (uint32_t)__cvta_generic_to_shared(&ws[1][0]);
    const char* wsrc = (const char*)g_wbf + (size_t)half * NCH_CTA * NCHUNK * DDIM * 2;

    for (int tile = 0; tile * TILE_M < len; ++tile) {
        __syncthreads();   // pooled2-init / previous-tile xs,ws drain
        // ---- stage x tile to bf16 smem (zero-pad ragged tail) ----
        {
            int row  = tid >> 1;
            int hh   = tid & 1;
            int rrem = len - tile * TILE_M;
            bool valid = row < rrem;
            const float* xr = x + ((size_t)(off + tile * TILE_M + row)) * DDIM + hh * 32;
            __nv_bfloat162* dst = (__nv_bfloat162*)&xs[row * XPITCH + hh * 32];
            #pragma unroll
            for (int j = 0; j < 8; ++j) {
                float4 v = valid ? __ldg((const float4*)xr + j)
                                 : make_float4(0.f, 0.f, 0.f, 0.f);
                dst[2 * j]     = __floats2bfloat162_rn(v.x, v.y);
                dst[2 * j + 1] = __floats2bfloat162_rn(v.z, v.w);
            }
        }
        // ---- cp.async chunk 0 ----
        {
            #pragma unroll
            for (int j = 0; j < 2; ++j) {
                uint32_t u = tid + THREADS * j;      // 16B unit, 512 total
                uint32_t row = u >> 3, cu = u & 7;
                CP16(sm_ws0 + row * (WPITCH * 2) + cu * 16, wsrc + (size_t)u * 16);
            }
            CP_COMMIT();
        }
        __syncthreads();   // xs visible

        // ---- A fragments: 32 rows per warp, pinned across all chunks ----
        uint32_t afr[2][4][4];
        #pragma unroll
        for (int m = 0; m < 2; ++m) {
            const __nv_bfloat16* base =
                &xs[(rgrp * 32 + m * 16 + (lane & 15)) * XPITCH + (lane >> 4) * 8];
            #pragma unroll
            for (int k = 0; k < 4; ++k)
                ldsm_x4(afr[m][k][0], afr[m][k][1], afr[m][k][2], afr[m][k][3],
                        base + k * 16);
        }

        for (int c = 0; c < NCH_CTA; ++c) {
            CP_WAIT0();
            __syncthreads();   // B(c) visible; all warps done with B(c-1)

            if (c + 1 < NCH_CTA) {   // prefetch B(c+1)
                const char* src = wsrc + (size_t)(c + 1) * NCHUNK * DDIM * 2;
                uint32_t bb = ((c + 1) & 1) ? sm_ws1 : sm_ws0;
                #pragma unroll
                for (int j = 0; j < 2; ++j) {
                    uint32_t u = tid + THREADS * j;
                    uint32_t row = u >> 3, cu = u & 7;
                    CP16(bb + row * (WPITCH * 2) + cu * 16, src + (size_t)u * 16);
                }
                CP_COMMIT();
            }

            const __nv_bfloat16* wbuf = ws[c & 1];
            float rm[4];   // running row-maxes: rows r, r+8, r+16, r+24

            #pragma unroll
            for (int h = 0; h < 2; ++h) {
                // B frags for this h-block: 16 cols x 64 k
                uint32_t bfr[4][4];
                #pragma unroll
                for (int k = 0; k < 4; ++k) {
                    const __nv_bfloat16* bp =
                        &wbuf[(pg * 32 + h * 16 + (lane & 15)) * WPITCH
                              + k * 16 + (lane >> 4) * 8];
                    ldsm_x4(bfr[k][0], bfr[k][1], bfr[k][2], bfr[k][3], bp);
                }
                float acc[2][2][4];
                #pragma unroll
                for (int m = 0; m < 2; ++m)
                    #pragma unroll
                    for (int nl = 0; nl < 2; ++nl)
                        acc[m][nl][0] = acc[m][nl][1] = acc[m][nl][2] = acc[m][nl][3] = 0.f;
                #pragma unroll
                for (int k = 0; k < 4; ++k)
                    #pragma unroll
                    for (int m = 0; m < 2; ++m) {
                        mma_bf16(acc[m][0], afr[m][k], bfr[k][0], bfr[k][2]);
                        mma_bf16(acc[m][1], afr[m][k], bfr[k][1], bfr[k][3]);
                    }
                // fold this h-block into running row-maxes (overlaps next h MMAs)
                #pragma unroll
                for (int m = 0; m < 2; ++m) {
                    float lo = fmaxf(fmaxf(acc[m][0][0], acc[m][0][1]),
                                     fmaxf(acc[m][1][0], acc[m][1][1]));
                    float hi = fmaxf(fmaxf(acc[m][0][2], acc[m][0][3]),
                                     fmaxf(acc[m][1][2], acc[m][1][3]));
                    if (h == 0) { rm[m * 2] = lo; rm[m * 2 + 1] = hi; }
                    else { rm[m * 2] = fmaxf(rm[m * 2], lo);
                           rm[m * 2 + 1] = fmaxf(rm[m * 2 + 1], hi); }
                }
            }

            // quad-max per row (covers all 32 cols of this p-group)
            #pragma unroll
            for (int r = 0; r < 4; ++r) {
                rm[r] = fmaxf(rm[r], __shfl_xor_sync(0xffffffffu, rm[r], 1));
                rm[r] = fmaxf(rm[r], __shfl_xor_sync(0xffffffffu, rm[r], 2));
            }
            float s4 = (rm[0] + rm[1]) + (rm[2] + rm[3]);   // 4 rows, this thread
            // exclusive-owner accumulate: warp (c,pg,rgrp), quad slot lane>>2
            if ((lane & 3) == 0)
                pooled2[(c * 2 + pg) * 32 + rgrp * 8 + (lane >> 2)] += s4;
        }
    }

    // ---- CTA-end reduction: 64 p x 32 slots -> out (unnormalized) ----
    __syncthreads();
    {
        int pl = tid >> 2, q = tid & 3;
        const float* row = &pooled2[pl * 32 + q * 8];
        float s = 0.f;
        #pragma unroll
        for (int j = 0; j < 8; ++j) s += row[j];
        s += __shfl_xor_sync(0xffffffffu, s, 1);
        s += __shfl_xor_sync(0xffffffffu, s, 2);
        if (q == 0) out[(size_t)b * PDIM + half * 64 + pl] = s;
    }
}

// ---------------- normalize kernel ----------------
__global__ void norm_kernel(float* __restrict__ out) {
    __shared__ float red[4];
    int b = blockIdx.x, t = threadIdx.x;   // 128 threads
    float v = out[(size_t)b * PDIM + t];
    float s2 = v * v;
    #pragma unroll
    for (int o = 16; o > 0; o >>= 1) s2 += __shfl_xor_sync(0xffffffffu, s2, o);
    if ((t & 31) == 0) red[t >> 5] = s2;
    __syncthreads();
    float nrm = sqrtf(red[0] + red[1] + red[2] + red[3]);
    out[(size_t)b * PDIM + t] = v / fmaxf(nrm, 1e-12f);
}

// ---------------- launch ----------------
extern "C" void kernel_launch(void* const* d_in, const int* in_sizes, int n_in,
                              void* d_out, int out_size) {
    const float* x     = (const float*)d_in[0];
    const float* w     = (const float*)d_in[1];
    const int*   index = (const int*)d_in[2];
    float* out = (float*)d_out;

    int nw = in_sizes[1];            // P*E*D = 262144
    int B  = in_sizes[2];            // 1024

    int n8 = nw / 8;
    prep_kernel<<<129, 256>>>(w, n8, index, B);
    main_kernel<<<2 * B, THREADS>>>(x, index, out);
    norm_kernel<<<B, 128>>>(out);
}

// round 9
// speedup vs baseline: 2.9046x; 1.3257x over previous
#include <cuda_runtime.h>
#include <cuda_bf16.h>
#include <cstdint>
#include <math.h>

// ---------------- problem constants ----------------
#define PDIM   128              // n_proxy_sets
#define EDIM   32               // elements per proxy set
#define DDIM   64               // feature dim
#define PE     (PDIM*EDIM)      // 4096 flattened proxies
#define NCHUNK 64               // proxies per chunk (= 2 proxy sets)
#define NCH_CTA 32              // chunks per CTA (proxy range split across 2 CTAs)
#define TILE_M 128              // x rows per tile
#define XPITCH 72               // padded bf16 row pitch (conflict-free ldsm)
#define THREADS 256
#define MAXB   1024

// W pre-shuffled into per-thread mma-fragment order:
// uint4 index = ((cpg)*8 + f)*32 + lane,  cpg = chunk*2+pg (0..127), f = nl*2+half
// uint4 = {b0(k16=2h), b1(k16=2h), b0(k16=2h+1), b1(k16=2h+1)} for (lane,nl)
__device__ uint4 g_wfrag[PE * DDIM / 8];     // 512 KB (L2-hot)
__device__ int g_segoff[MAXB];

// ---------------- prep kernel: fragment-shuffle conversion + scan ----------------
__global__ void prep_kernel(const float* __restrict__ w,
                            const int* __restrict__ index, int B) {
    if (blockIdx.x < 128) {
        int id   = blockIdx.x * 256 + threadIdx.x;   // 0..32767 uint4s
        int lane = id & 31;
        int f    = (id >> 5) & 7;
        int cpg  = id >> 8;                          // 0..127
        int nl   = f >> 1, half = f & 1;
        int g    = lane >> 2, t = lane & 3;
        const float* wr = w + ((size_t)(cpg * 32 + nl * 8 + g)) * DDIM;
        int ka = half * 32;                          // k16=(2*half)*16
        __nv_bfloat162 x = __floats2bfloat162_rn(wr[ka +      t*2], wr[ka +      t*2 + 1]);
        __nv_bfloat162 y = __floats2bfloat162_rn(wr[ka +  8 + t*2], wr[ka +  8 + t*2 + 1]);
        __nv_bfloat162 z = __floats2bfloat162_rn(wr[ka + 16 + t*2], wr[ka + 16 + t*2 + 1]);
        __nv_bfloat162 u = __floats2bfloat162_rn(wr[ka + 24 + t*2], wr[ka + 24 + t*2 + 1]);
        uint4 pk;
        pk.x = *(uint32_t*)&x; pk.y = *(uint32_t*)&y;
        pk.z = *(uint32_t*)&z; pk.w = *(uint32_t*)&u;
        g_wfrag[id] = pk;
    } else {
        __shared__ int s[256];
        int t = threadIdx.x;
        int v[4]; int base = t * 4;
        int acc = 0;
        #pragma unroll
        for (int j = 0; j < 4; ++j) {
            v[j] = acc;
            int e = base + j;
            acc += (e < B) ? index[e] : 0;
        }
        s[t] = acc;
        __syncthreads();
        for (int o = 1; o < 256; o <<= 1) {
            int add = (t >= o) ? s[t - o] : 0;
            __syncthreads();
            s[t] += add;
            __syncthreads();
        }
        int pre = (t > 0) ? s[t - 1] : 0;
        #pragma unroll
        for (int j = 0; j < 4; ++j) {
            int e = base + j;
            if (e < B) g_segoff[e] = pre + v[j];
        }
    }
}

// ---------------- MMA primitives ----------------
__device__ __forceinline__ void ldsm_x4(uint32_t& r0, uint32_t& r1,
                                        uint32_t& r2, uint32_t& r3,
                                        const void* p) {
    uint32_t a = (uint32_t)__cvta_generic_to_shared(p);
    asm volatile("ldmatrix.sync.aligned.m8n8.x4.shared.b16 {%0,%1,%2,%3}, [%4];"
                 : "=r"(r0), "=r"(r1), "=r"(r2), "=r"(r3) : "r"(a));
}

__device__ __forceinline__ void mma_bf16(float* c, const uint32_t* a,
                                         uint32_t b0, uint32_t b1) {
    asm volatile(
        "mma.sync.aligned.m16n8k16.row.col.f32.bf16.bf16.f32 "
        "{%0,%1,%2,%3}, {%4,%5,%6,%7}, {%8,%9}, {%0,%1,%2,%3};"
        : "+f"(c[0]), "+f"(c[1]), "+f"(c[2]), "+f"(c[3])
        : "r"(a[0]), "r"(a[1]), "r"(a[2]), "r"(a[3]), "r"(b0), "r"(b1));
}

// one 16-col stage: 16 HMMAs from fragment-direct B regs, fold into rm
__device__ __forceinline__ void stage_compute(const uint4* bb,
                                              const uint32_t afr[2][4][4],
                                              float rm[4], bool first) {
    float acc[2][2][4];
    #pragma unroll
    for (int m = 0; m < 2; ++m)
        #pragma unroll
        for (int nlh = 0; nlh < 2; ++nlh)
            acc[m][nlh][0] = acc[m][nlh][1] = acc[m][nlh][2] = acc[m][nlh][3] = 0.f;

    #pragma unroll
    for (int k16 = 0; k16 < 4; ++k16) {
        #pragma unroll
        for (int nlh = 0; nlh < 2; ++nlh) {
            uint4 v = bb[nlh * 2 + (k16 >> 1)];
            uint32_t b0 = (k16 & 1) ? v.z : v.x;
            uint32_t b1 = (k16 & 1) ? v.w : v.y;
            mma_bf16(acc[0][nlh], afr[0][k16], b0, b1);
            mma_bf16(acc[1][nlh], afr[1][k16], b0, b1);
        }
    }
    #pragma unroll
    for (int m = 0; m < 2; ++m) {
        float lo = fmaxf(fmaxf(acc[m][0][0], acc[m][0][1]),
                         fmaxf(acc[m][1][0], acc[m][1][1]));
        float hi = fmaxf(fmaxf(acc[m][0][2], acc[m][0][3]),
                         fmaxf(acc[m][1][2], acc[m][1][3]));
        if (first) { rm[m * 2] = lo; rm[m * 2 + 1] = hi; }
        else       { rm[m * 2] = fmaxf(rm[m * 2], lo);
                     rm[m * 2 + 1] = fmaxf(rm[m * 2 + 1], hi); }
    }
}

#define LOAD4(dst, ptr) do {                     \
    (dst)[0] = __ldg((ptr));                     \
    (dst)[1] = __ldg((ptr) + 32);                \
    (dst)[2] = __ldg((ptr) + 64);                \
    (dst)[3] = __ldg((ptr) + 96); } while (0)

// ---------------- main kernel ----------------
// 2 CTAs per segment; each sweeps 32 proxy chunks. 8 warps = 4 rgrp x 2 pg.
// B fragments read DIRECTLY from g_wfrag via coalesced LDG.128 (no smem, no
// barriers in the chunk loop) with a 2-stage register pipeline per chunk.
// A frags pinned in regs per tile. Per-chunk: quad-max + exclusive-owner
// smem += into pooled2; CTA-end reduction -> out (unnormalized); norm_kernel
// finishes.
__global__ __launch_bounds__(THREADS, 2)
void main_kernel(const float* __restrict__ x, const int* __restrict__ index,
                 float* __restrict__ out) {
    __shared__ __nv_bfloat16 xs[TILE_M * XPITCH];   // 18 KB
    __shared__ float pooled2[64 * 32];              // 8 KB [p_local][slot]

    const int b    = blockIdx.x >> 1;
    const int half = blockIdx.x & 1;
    const int tid  = threadIdx.x;
    const int lane = tid & 31;
    const int warp = tid >> 5;
    const int rgrp = warp & 3;     // row-group (32 rows)
    const int pg   = warp >> 2;    // proxy-group within chunk (0/1)

    for (int i = tid; i < 64 * 32; i += THREADS) pooled2[i] = 0.f;

    const int off = g_segoff[b];
    const int len = index[b];

    // this warp's fragment stream: half selects 32-chunk range; chunk stride 512 u4
    const uint4* wf = g_wfrag + (size_t)half * 16384 + pg * 256 + lane;

    for (int tile = 0; tile * TILE_M < len; ++tile) {
        __syncthreads();   // pooled2 init / previous tile xs drain
        // ---- stage x tile to bf16 smem (zero-pad ragged tail) ----
        {
            int row  = tid >> 1;
            int hh   = tid & 1;
            int rrem = len - tile * TILE_M;
            bool valid = row < rrem;
            const float* xr = x + ((size_t)(off + tile * TILE_M + row)) * DDIM + hh * 32;
            __nv_bfloat162* dst = (__nv_bfloat162*)&xs[row * XPITCH + hh * 32];
            #pragma unroll
            for (int j = 0; j < 8; ++j) {
                float4 v = valid ? __ldg((const float4*)xr + j)
                                 : make_float4(0.f, 0.f, 0.f, 0.f);
                dst[2 * j]     = __floats2bfloat162_rn(v.x, v.y);
                dst[2 * j + 1] = __floats2bfloat162_rn(v.z, v.w);
            }
        }
        __syncthreads();   // xs visible

        // ---- A fragments: 32 rows per warp, pinned across all chunks ----
        uint32_t afr[2][4][4];
        #pragma unroll
        for (int m = 0; m < 2; ++m) {
            const __nv_bfloat16* base =
                &xs[(rgrp * 32 + m * 16 + (lane & 15)) * XPITCH + (lane >> 4) * 8];
            #pragma unroll
            for (int k = 0; k < 4; ++k)
                ldsm_x4(afr[m][k][0], afr[m][k][1], afr[m][k][2], afr[m][k][3],
                        base + k * 16);
        }

        // ---- barrier-free chunk sweep, 2-stage register pipeline ----
        uint4 bufA[4], bufB[4];
        LOAD4(bufA, wf);                      // chunk 0, stage 0
        for (int c = 0; c < NCH_CTA; ++c) {
            const uint4* cbase = wf + c * 512;
            // prefetch stage 1 of chunk c, then compute stage 0
            LOAD4(bufB, cbase + 128);
            float rm[4];
            stage_compute(bufA, afr, rm, true);
            // prefetch stage 0 of chunk c+1, then compute stage 1
            if (c + 1 < NCH_CTA) LOAD4(bufA, cbase + 512);
            stage_compute(bufB, afr, rm, false);

            // quad-max per row (covers all 32 cols of this p-group)
            #pragma unroll
            for (int r = 0; r < 4; ++r) {
                rm[r] = fmaxf(rm[r], __shfl_xor_sync(0xffffffffu, rm[r], 1));
                rm[r] = fmaxf(rm[r], __shfl_xor_sync(0xffffffffu, rm[r], 2));
            }
            float s4 = (rm[0] + rm[1]) + (rm[2] + rm[3]);   // 4 rows, this thread
            // exclusive-owner accumulate (no atomics, no shuffle-to-lane0)
            if ((lane & 3) == 0)
                pooled2[(c * 2 + pg) * 32 + rgrp * 8 + (lane >> 2)] += s4;
        }
    }

    // ---- CTA-end reduction: 64 p x 32 slots -> out (unnormalized) ----
    __syncthreads();
    {
        int pl = tid >> 2, q = tid & 3;
        const float* row = &pooled2[pl * 32 + q * 8];
        float s = 0.f;
        #pragma unroll
        for (int j = 0; j < 8; ++j) s += row[j];
        s += __shfl_xor_sync(0xffffffffu, s, 1);
        s += __shfl_xor_sync(0xffffffffu, s, 2);
        if (q == 0) out[(size_t)b * PDIM + half * 64 + pl] = s;
    }
}

// ---------------- normalize kernel ----------------
__global__ void norm_kernel(float* __restrict__ out) {
    __shared__ float red[4];
    int b = blockIdx.x, t = threadIdx.x;   // 128 threads
    float v = out[(size_t)b * PDIM + t];
    float s2 = v * v;
    #pragma unroll
    for (int o = 16; o > 0; o >>= 1) s2 += __shfl_xor_sync(0xffffffffu, s2, o);
    if ((t & 31) == 0) red[t >> 5] = s2;
    __syncthreads();
    float nrm = sqrtf(red[0] + red[1] + red[2] + red[3]);
    out[(size_t)b * PDIM + t] = v / fmaxf(nrm, 1e-12f);
}

// ---------------- launch ----------------
extern "C" void kernel_launch(void* const* d_in, const int* in_sizes, int n_in,
                              void* d_out, int out_size) {
    const float* x     = (const float*)d_in[0];
    const float* w     = (const float*)d_in[1];
    const int*   index = (const int*)d_in[2];
    float* out = (float*)d_out;

    int B = in_sizes[2];             // 1024

    prep_kernel<<<129, 256>>>(w, index, B);
    main_kernel<<<2 * B, THREADS>>>(x, index, out);
    norm_kernel<<<B, 128>>>(out);
}